// round 3
// baseline (speedup 1.0000x reference)
#include <cuda_runtime.h>
#include <math.h>

// Problem dims (fixed)
#define B_   128
#define T_   500
#define NI_  256
#define N_   256
#define M_   (B_*T_)
#define TBN_ ((size_t)T_*B_*N_)

// xw scratch (natural [M][N] layout)
__device__ float g_xw[(size_t)M_ * N_];

// Packed fp32x2 helpers
#define FFMA2(d, a, b, c) \
    asm("fma.rn.f32x2 %0, %1, %2, %3;" : "=l"(d) : "l"(a), "l"(b), "l"(c))
#define PACK2(d, s) \
    asm("mov.b64 %0, {%1, %1};" : "=l"(d) : "f"(s))

// ===========================================================================
// Kernel 1: xw = x @ w_in. BM=128, BN=256, BK=16, 256 thr, 8m x 16n microtile
// with pair-accumulators over N (A splat-packed: 8 movs/k instead of 16).
// Persistent: 125 CTAs x 4 tiles (single wave, no tail).
// ===========================================================================
#define ASTRIDE 132
#define ASZ (2*16*ASTRIDE)
#define BSZ (2*16*256)
#define GEMM_SMEM ((ASZ + BSZ) * 4)
#define TILES_PER_CTA 4

__global__ void __launch_bounds__(256, 1)
gemm_xw(const float* __restrict__ A, const float* __restrict__ W)
{
    extern __shared__ float gsm[];
    float* As = gsm;          // [2][16][132]  (k-major, m inner)
    float* Bs = gsm + ASZ;    // [2][16][256]

    const int t  = threadIdx.x;
    const int tn = t & 15;
    const int m0 = (t >> 4) << 3;     // 8 m-rows per thread
    const int ar = t >> 2;            // A-load row (and ar+64)
    const int kc = (t & 3) << 2;      // A-load k quad

#pragma unroll 1
    for (int tile = 0; tile < TILES_PER_CTA; tile++) {
        const int bm = (blockIdx.x * TILES_PER_CTA + tile) << 7;

        unsigned long long acc[8][8];
#pragma unroll
        for (int e = 0; e < 8; e++)
#pragma unroll
            for (int j = 0; j < 8; j++) acc[e][j] = 0ull;

        __syncthreads();   // protect smem reuse across tiles

        // ---- prologue: k-tile 0 into stage 0 ----
        float4 ra0 = *(const float4*)(A + (size_t)(bm + ar) * NI_ + kc);
        float4 ra1 = *(const float4*)(A + (size_t)(bm + ar + 64) * NI_ + kc);
#pragma unroll
        for (int i = 0; i < 4; i++) {
            int id = t + (i << 8), bk = id >> 6, bn = (id & 63) << 2;
            unsigned dst = (unsigned)__cvta_generic_to_shared(Bs + bk * 256 + bn);
            asm volatile("cp.async.cg.shared.global [%0], [%1], 16;"
                         :: "r"(dst), "l"(W + (size_t)bk * N_ + bn));
        }
        asm volatile("cp.async.commit_group;");
        As[(kc+0)*ASTRIDE + ar] = ra0.x;  As[(kc+1)*ASTRIDE + ar] = ra0.y;
        As[(kc+2)*ASTRIDE + ar] = ra0.z;  As[(kc+3)*ASTRIDE + ar] = ra0.w;
        As[(kc+0)*ASTRIDE + ar+64] = ra1.x;  As[(kc+1)*ASTRIDE + ar+64] = ra1.y;
        As[(kc+2)*ASTRIDE + ar+64] = ra1.z;  As[(kc+3)*ASTRIDE + ar+64] = ra1.w;
        asm volatile("cp.async.wait_group 0;");
        __syncthreads();

#pragma unroll 1
        for (int kt = 0; kt < 16; kt++) {
            const int st = kt & 1;
            if (kt < 15) {
                ra0 = *(const float4*)(A + (size_t)(bm + ar) * NI_
                                         + (kt + 1) * 16 + kc);
                ra1 = *(const float4*)(A + (size_t)(bm + ar + 64) * NI_
                                         + (kt + 1) * 16 + kc);
#pragma unroll
                for (int i = 0; i < 4; i++) {
                    int id = t + (i << 8), bk = id >> 6, bn = (id & 63) << 2;
                    unsigned dst = (unsigned)__cvta_generic_to_shared(
                        Bs + (st ^ 1) * (16 * 256) + bk * 256 + bn);
                    asm volatile("cp.async.cg.shared.global [%0], [%1], 16;"
                        :: "r"(dst), "l"(W + (size_t)((kt+1)*16 + bk) * N_ + bn));
                }
                asm volatile("cp.async.commit_group;");
            }

            const float* as = As + st * (16 * ASTRIDE);
            const float* bs = Bs + st * (16 * 256);
#pragma unroll
            for (int k = 0; k < 16; k++) {
                float4 aL = *(const float4*)(as + k * ASTRIDE + m0);
                float4 aH = *(const float4*)(as + k * ASTRIDE + m0 + 4);
                unsigned long long ap[8];
                PACK2(ap[0], aL.x); PACK2(ap[1], aL.y);
                PACK2(ap[2], aL.z); PACK2(ap[3], aL.w);
                PACK2(ap[4], aH.x); PACK2(ap[5], aH.y);
                PACK2(ap[6], aH.z); PACK2(ap[7], aH.w);
#pragma unroll
                for (int c = 0; c < 4; c++) {
                    ulonglong2 bv = *(const ulonglong2*)(bs + k * 256
                                                         + (c << 6) + (tn << 2));
#pragma unroll
                    for (int e = 0; e < 8; e++) {
                        FFMA2(acc[e][2*c],   ap[e], bv.x, acc[e][2*c]);
                        FFMA2(acc[e][2*c+1], ap[e], bv.y, acc[e][2*c+1]);
                    }
                }
            }
            if (kt == 15) break;

            float* ad = As + (st ^ 1) * (16 * ASTRIDE);
            ad[(kc+0)*ASTRIDE + ar] = ra0.x;  ad[(kc+1)*ASTRIDE + ar] = ra0.y;
            ad[(kc+2)*ASTRIDE + ar] = ra0.z;  ad[(kc+3)*ASTRIDE + ar] = ra0.w;
            ad[(kc+0)*ASTRIDE + ar+64] = ra1.x;  ad[(kc+1)*ASTRIDE + ar+64] = ra1.y;
            ad[(kc+2)*ASTRIDE + ar+64] = ra1.z;  ad[(kc+3)*ASTRIDE + ar+64] = ra1.w;
            asm volatile("cp.async.wait_group 0;");
            __syncthreads();
        }

        // ---- epilogue: natural row-major xw ----
#pragma unroll
        for (int e = 0; e < 8; e++) {
            float* rp = g_xw + (size_t)(bm + m0 + e) * N_;
#pragma unroll
            for (int c = 0; c < 4; c++) {
                ulonglong2 s;
                s.x = acc[e][2*c]; s.y = acc[e][2*c+1];
                *(ulonglong2*)(rp + (c << 6) + (tn << 2)) = s;
            }
        }
    }
}

// ===========================================================================
// Kernel 2: LSNN scan, 512 threads (2 threads per neuron).
//  - w_rec rows [0,220) + zero sentinel row 220 in smem; rows [220,256) in
//    registers (18 per half).
//  - Per-warp fixed-base sentinel-padded segments (no cross-warp prefix).
//  - Half 0 (tid<256): gather segs 0-2 + reg rows 0-17, dynamics, ballot,
//    list+dyn writes. Half 1: gather segs 3-6 + reg rows 18-35, partial sum,
//    lagged v_sc/div + all 4 output stores for step t-1.
//  - 2 barriers/step. zf via compare (no div on the recurrence path).
// ===========================================================================
#define WROWS    220
#define SENT_OFF (220 << 10)
#define SCAN_FLOATS (221*256 + 252 + 8 + 8 + 256 + 256 + 256)
#define SCAN_SMEM   (SCAN_FLOATS * 4)     // 230448 B

#define GATHER_SEG(s, c4v) do {                                   \
    const int* lp = segL + (s) * 36;                              \
    int   c4_ = (c4v);                                            \
    int4  o_  = *(const int4*)lp;                                 \
    for (int j_ = 1; j_ <= c4_; j_++) {                           \
        int4 nx_ = *(const int4*)(lp + 4 * j_);                   \
        accv[0] += *(const float*)(wpn + o_.x);                   \
        accv[1] += *(const float*)(wpn + o_.y);                   \
        accv[2] += *(const float*)(wpn + o_.z);                   \
        accv[3] += *(const float*)(wpn + o_.w);                   \
        o_ = nx_;                                                 \
    }                                                             \
} while (0)

__global__ void __launch_bounds__(512, 1)
lsnn_scan(const float* __restrict__ w_rec,
          const float* __restrict__ z0,  const float* __restrict__ v0,
          const float* __restrict__ a0,  const float* __restrict__ lsd0,
          float* __restrict__ out, float decay_v, float decay_a)
{
    extern __shared__ float sm[];
    float*    w_sm    = sm;                              // [221][256]
    int*      segL    = (int*)(sm + 221 * 256);          // [7][36]
    int*      cnt4s   = segL + 252;                      // [8] (seg chunk cnt)
    unsigned* masksS  = (unsigned*)(cnt4s + 8);          // [8] warp ballots
    float*    partial = (float*)(masksS + 8);            // [256]
    float*    dynV    = partial + 256;                   // [256]
    float*    dynT    = dynV + 256;                      // [256]

    const int tid  = threadIdx.x;
    const int n    = tid & 255;
    const int half = tid >> 8;
    const int w    = n >> 5;
    const int lane = n & 31;
    const int b    = blockIdx.x;

    // weights rows 0..219 -> smem
    {
        const float4* src = (const float4*)w_rec;
        float4*       dst = (float4*)w_sm;
        for (int i = tid; i < WROWS * 64; i += 512) dst[i] = src[i];
    }
    // register rows: half h holds rows 220+18h .. 220+18h+17
    float wreg[18];
    const int rbase = WROWS + half * 18;
#pragma unroll
    for (int j = 0; j < 18; j++) wreg[j] = w_rec[(size_t)(rbase + j) * 256 + n];
#pragma unroll
    for (int j = 0; j < 18; j++)
        if (n == rbase + j) wreg[j] = 0.f;               // diag mask (reg rows)
    if (half == 0) w_sm[WROWS * 256 + n] = 0.f;          // zero sentinel row
    __syncthreads();
    if (tid < WROWS) w_sm[tid * 256 + tid] = 0.f;        // diag mask (smem rows)

    float z_self = 0.f, v = 0.f, a = 0.f, lsd = 0.f;
    if (half == 0) {
        z_self = z0[b * N_ + n];  v   = v0[b * N_ + n];
        a      = a0[b * N_ + n];  lsd = lsd0[b * N_ + n];
        // initial list build from z0
        unsigned m    = __ballot_sync(0xffffffffu, z_self != 0.f);
        unsigned mseg = (w == 6) ? (m & 0x0FFFFFFFu) : m;
        if (w < 7) {
            int cnt = __popc(mseg);
            if ((mseg >> lane) & 1u) {
                int pos = __popc(mseg & ((1u << lane) - 1u));
                segL[w * 36 + pos] = n << 10;
            }
            int c4 = (cnt + 3) >> 2, extra = (c4 << 2) - cnt;
            if (lane < extra) segL[w * 36 + cnt + lane] = SENT_OFF;
            if (lane == 0) { cnt4s[w] = c4; masksS[w] = m; }
        } else if (lane == 0) masksS[7] = m;
    }
    __syncthreads();

    const float omdv = 1.f - decay_v;
    const float omda = 1.f - decay_a;
    const char*  wpn = (const char*)w_sm + (n << 2);
    const float* xwp = g_xw + (size_t)b * T_ * N_ + n;

    float xw_cur = (half == 0) ? __ldcs(xwp) : 0.f;
    float xw_nxt = 0.f;
    float pv = 0.f, pt = 0.f;
    unsigned pm = 0u;

#pragma unroll 1
    for (int t = 0; t < T_; t++) {
        float accv[4] = {0.f, 0.f, 0.f, 0.f};

        if (half == 0) {
            xw_nxt = (t + 1 < T_) ? __ldcs(xwp + (size_t)(t + 1) * N_) : 0.f;
            unsigned m6 = masksS[6], m7 = masksS[7];
            int4 cA = *(const int4*)cnt4s;
            GATHER_SEG(0, cA.x);
            GATHER_SEG(1, cA.y);
            GATHER_SEG(2, cA.z);
            unsigned R = ((m6 >> 28) & 0xFu) | ((m7 & 0x3FFFu) << 4);
#pragma unroll
            for (int j = 0; j < 18; j++)
                if (R & (1u << j)) accv[j & 3] += wreg[j];
        } else {
            pv = dynV[n]; pt = dynT[n]; pm = masksS[w];
            unsigned m7 = masksS[7];
            int4 cA = *(const int4*)cnt4s;
            int4 cB = *(const int4*)(cnt4s + 4);
            GATHER_SEG(3, cA.w);
            GATHER_SEG(4, cB.x);
            GATHER_SEG(5, cB.y);
            GATHER_SEG(6, cB.z);
            unsigned R = m7 >> 14;
#pragma unroll
            for (int j = 0; j < 18; j++)
                if (R & (1u << j)) accv[j & 3] += wreg[j];
            partial[n] = __fadd_rn(__fadd_rn(accv[0], accv[1]),
                                   __fadd_rn(accv[2], accv[3]));
        }
        __syncthreads();   // mid bar

        if (half == 0) {
            float prt  = partial[n];
            float i_in = __fadd_rn(__fadd_rn(xw_cur, prt),
                          __fadd_rn(__fadd_rn(accv[0], accv[1]),
                                    __fadd_rn(accv[2], accv[3])));
            float new_a = __fadd_rn(__fmul_rn(decay_a, a),
                                    __fmul_rn(omda, z_self));
            float thr   = __fadd_rn(0.03f, __fmul_rn(new_a, 1.8f));
            float new_v = __fadd_rn(
                            __fadd_rn(__fmul_rn(decay_v, v),
                                      __fmul_rn(omdv, i_in)),
                            __fmul_rn(-thr, z_self));
            int   spk = (new_v > thr) && (lsd >= 2.f);   // sign-exact, no div
            float zf  = spk ? 1.f : 0.f;
            float new_lsd = __fmul_rn(__fadd_rn(lsd, 1.f),
                                      __fadd_rn(1.f, -zf));

            unsigned m    = __ballot_sync(0xffffffffu, spk);
            unsigned mseg = (w == 6) ? (m & 0x0FFFFFFFu) : m;
            if (w < 7) {
                int cnt = __popc(mseg);
                if ((mseg >> lane) & 1u) {
                    int pos = __popc(mseg & ((1u << lane) - 1u));
                    segL[w * 36 + pos] = n << 10;
                }
                int c4 = (cnt + 3) >> 2, extra = (c4 << 2) - cnt;
                if (lane < extra) segL[w * 36 + cnt + lane] = SENT_OFF;
                if (lane == 0) { cnt4s[w] = c4; masksS[w] = m; }
            } else if (lane == 0) masksS[7] = m;

            dynV[n] = new_v;  dynT[n] = thr;
            z_self = zf; v = new_v; a = new_a; lsd = new_lsd;
            xw_cur = xw_nxt;
        } else if (t > 0) {
            // lagged outputs of step t-1 (values read pre-mid this step)
            float pz   = ((pm >> lane) & 1u) ? 1.f : 0.f;
            float pvsc = __fdividef(__fadd_rn(pv, -pt), pt);
            size_t ob  = ((size_t)(t - 1) * B_ + b) * N_ + n;
            __stcs(out + ob,            pz);
            __stcs(out + TBN_ + ob,     pv);
            __stcs(out + 2 * TBN_ + ob, pt);
            __stcs(out + 3 * TBN_ + ob, pvsc);
        }
        __syncthreads();   // end bar
    }

    // tail: outputs of step T-1
    if (half == 1) {
        float pv2 = dynV[n], pt2 = dynT[n];
        unsigned pm2 = masksS[w];
        float pz   = ((pm2 >> lane) & 1u) ? 1.f : 0.f;
        float pvsc = __fdividef(__fadd_rn(pv2, -pt2), pt2);
        size_t ob  = ((size_t)(T_ - 1) * B_ + b) * N_ + n;
        __stcs(out + ob,            pz);
        __stcs(out + TBN_ + ob,     pv2);
        __stcs(out + 2 * TBN_ + ob, pt2);
        __stcs(out + 3 * TBN_ + ob, pvsc);
    }
}

// ---------------------------------------------------------------------------
// Launcher (graph-capturable)
// ---------------------------------------------------------------------------
extern "C" void kernel_launch(void* const* d_in, const int* in_sizes, int n_in,
                              void* d_out, int out_size)
{
    const float* x     = (const float*)d_in[0];
    const float* w_in  = (const float*)d_in[1];
    const float* w_rec = (const float*)d_in[2];
    const float* z0    = (const float*)d_in[3];
    const float* v0    = (const float*)d_in[4];
    const float* a0    = (const float*)d_in[5];
    const float* lsd0  = (const float*)d_in[6];
    float* out = (float*)d_out;

    const float decay_v = expf(-1.0f / 20.0f);
    const float decay_a = expf(-1.0f / 20.0f);

    cudaFuncSetAttribute(gemm_xw,
                         cudaFuncAttributeMaxDynamicSharedMemorySize, GEMM_SMEM);
    cudaFuncSetAttribute(lsnn_scan,
                         cudaFuncAttributeMaxDynamicSharedMemorySize, SCAN_SMEM);

    gemm_xw<<<M_ / 128 / TILES_PER_CTA, 256, GEMM_SMEM>>>(x, w_in);
    lsnn_scan<<<B_, 512, SCAN_SMEM>>>(w_rec, z0, v0, a0, lsd0, out,
                                      decay_v, decay_a);
}

// round 4
// speedup vs baseline: 1.8824x; 1.8824x over previous
#include <cuda_runtime.h>
#include <math.h>

// Problem dims (fixed)
#define B_   128
#define T_   500
#define NI_  256
#define N_   256
#define M_   (B_*T_)
#define TBN_ ((size_t)T_*B_*N_)

// xw scratch, m-pair interleaved: ULL index p*256+n holds (xw[2p][n], xw[2p+1][n])
__device__ unsigned long long g_xw[(size_t)M_ * N_ / 2];

// Packed fp32x2 helpers
#define FFMA2(d, a, b, c) \
    asm("fma.rn.f32x2 %0, %1, %2, %3;" : "=l"(d) : "l"(a), "l"(b), "l"(c))
#define PACK2(d, s) \
    asm("mov.b64 %0, {%1, %1};" : "=l"(d) : "f"(s))

// ===========================================================================
// Kernel 1: xw = x @ w_in. BM=128, BN=256, BK=16, 256 thr, 4m x 16n microtile
// (R2 version, verbatim: measured 188us).
// ===========================================================================
#define ASTRIDE 132
#define ASZ (2*16*ASTRIDE)
#define BSZ (2*16*256)
#define GEMM_SMEM ((ASZ + BSZ) * 4)

__global__ void __launch_bounds__(256, 1)
gemm_xw(const float* __restrict__ A, const float* __restrict__ W)
{
    extern __shared__ float gsm[];
    float* As = gsm;          // [2][16][132]
    float* Bs = gsm + ASZ;    // [2][16][256]

    const int t  = threadIdx.x;
    const int bm = blockIdx.x << 7;
    const int tm = t >> 4, tn = t & 15;
    const int m0 = tm << 3;

    const int amr[2] = { (t) >> 2, (t + 256) >> 2 };
    const int akc[2] = { (t & 3) << 2, (t & 3) << 2 };

    unsigned long long acc[4][16];
#pragma unroll
    for (int e = 0; e < 4; e++)
#pragma unroll
        for (int j = 0; j < 16; j++) acc[e][j] = 0ull;

    float4 ra[2];

#pragma unroll
    for (int i = 0; i < 2; i++)
        ra[i] = *(const float4*)(A + (size_t)(bm + amr[i]) * NI_ + akc[i]);
#pragma unroll
    for (int i = 0; i < 4; i++) {
        int id = t + (i << 8), bk = id >> 6, bn = (id & 63) << 2;
        unsigned dst = (unsigned)__cvta_generic_to_shared(Bs + bk * 256 + bn);
        asm volatile("cp.async.cg.shared.global [%0], [%1], 16;"
                     :: "r"(dst), "l"(W + (size_t)bk * N_ + bn));
    }
    asm volatile("cp.async.commit_group;");
#pragma unroll
    for (int i = 0; i < 2; i++) {
        As[(akc[i] + 0) * ASTRIDE + amr[i]] = ra[i].x;
        As[(akc[i] + 1) * ASTRIDE + amr[i]] = ra[i].y;
        As[(akc[i] + 2) * ASTRIDE + amr[i]] = ra[i].z;
        As[(akc[i] + 3) * ASTRIDE + amr[i]] = ra[i].w;
    }
    asm volatile("cp.async.wait_group 0;");
    __syncthreads();

    for (int kt = 0; kt < 16; kt++) {
        const int st = kt & 1;
        if (kt < 15) {
#pragma unroll
            for (int i = 0; i < 2; i++)
                ra[i] = *(const float4*)(A + (size_t)(bm + amr[i]) * NI_
                                           + (kt + 1) * 16 + akc[i]);
#pragma unroll
            for (int i = 0; i < 4; i++) {
                int id = t + (i << 8), bk = id >> 6, bn = (id & 63) << 2;
                unsigned dst = (unsigned)__cvta_generic_to_shared(
                    Bs + (st ^ 1) * (16 * 256) + bk * 256 + bn);
                asm volatile("cp.async.cg.shared.global [%0], [%1], 16;"
                    :: "r"(dst), "l"(W + (size_t)((kt+1)*16 + bk) * N_ + bn));
            }
            asm volatile("cp.async.commit_group;");
        }

        const float* as = As + st * (16 * ASTRIDE);
        const float* bs = Bs + st * (16 * 256);
#pragma unroll
        for (int k = 0; k < 16; k++) {
            ulonglong2 aA = *(const ulonglong2*)(as + k * ASTRIDE + m0);
            ulonglong2 aB = *(const ulonglong2*)(as + k * ASTRIDE + m0 + 4);
            unsigned long long am4[4] = { aA.x, aA.y, aB.x, aB.y };
#pragma unroll
            for (int c = 0; c < 4; c++) {
                float4 bv = *(const float4*)(bs + k * 256 + (c << 6) + (tn << 2));
                unsigned long long b0, b1, b2, b3;
                PACK2(b0, bv.x); PACK2(b1, bv.y);
                PACK2(b2, bv.z); PACK2(b3, bv.w);
#pragma unroll
                for (int e = 0; e < 4; e++) {
                    FFMA2(acc[e][4*c+0], am4[e], b0, acc[e][4*c+0]);
                    FFMA2(acc[e][4*c+1], am4[e], b1, acc[e][4*c+1]);
                    FFMA2(acc[e][4*c+2], am4[e], b2, acc[e][4*c+2]);
                    FFMA2(acc[e][4*c+3], am4[e], b3, acc[e][4*c+3]);
                }
            }
        }
        if (kt == 15) break;

#pragma unroll
        for (int i = 0; i < 2; i++) {
            float* ad = As + (st ^ 1) * (16 * ASTRIDE);
            ad[(akc[i] + 0) * ASTRIDE + amr[i]] = ra[i].x;
            ad[(akc[i] + 1) * ASTRIDE + amr[i]] = ra[i].y;
            ad[(akc[i] + 2) * ASTRIDE + amr[i]] = ra[i].z;
            ad[(akc[i] + 3) * ASTRIDE + amr[i]] = ra[i].w;
        }
        asm volatile("cp.async.wait_group 0;");
        __syncthreads();
    }

    unsigned long long* op = g_xw;
    const int pbase = (bm + m0) >> 1;
#pragma unroll
    for (int e = 0; e < 4; e++) {
        size_t prow = (size_t)(pbase + e) * 256;
#pragma unroll
        for (int c = 0; c < 4; c++) {
            int ncol = (c << 6) + (tn << 2);
            ulonglong2 s0, s1;
            s0.x = acc[e][4*c+0]; s0.y = acc[e][4*c+1];
            s1.x = acc[e][4*c+2]; s1.y = acc[e][4*c+3];
            *(ulonglong2*)(op + prow + ncol)     = s0;
            *(ulonglong2*)(op + prow + ncol + 2) = s1;
        }
    }
}

// ===========================================================================
// Kernel 2: LSNN scan (R2 structure) with block-read gather:
// flat list padded to >=32 entries with sentinels; first 8 offset chunks read
// unconditionally as independent int4 broadcasts -> 32 independent weight LDS
// into 8 acc chains; rare tail loop for tot>32. Spike via compare (div moved
// off the recurrence path).
// ===========================================================================
#define WROWS 224
#define SENT  (224 << 10)
#define LCAP  240
#define SCAN_SMEM (225*256*4 + 2*LCAP*4 + 16*4 + 2*4 + 2*4)   // 232400 B

__global__ void __launch_bounds__(256, 1)
lsnn_scan(const float* __restrict__ w_rec,
          const float* __restrict__ z0,  const float* __restrict__ v0,
          const float* __restrict__ a0,  const float* __restrict__ lsd0,
          float* __restrict__ out, float decay_v, float decay_a)
{
    extern __shared__ float sm[];
    float*    w_sm  = sm;                          // [225][256], row 224 = zeros
    int*      flatL = (int*)(sm + 225 * 256);      // [2][LCAP]
    int*      cntS  = flatL + 2 * LCAP;            // [2][8]
    unsigned* maskH = (unsigned*)(cntS + 16);      // [2]
    int*      totS  = (int*)(maskH + 2);           // [2]

    const int b    = blockIdx.x;
    const int n    = threadIdx.x;
    const int w    = n >> 5;
    const int lane = n & 31;

    // weights rows 0..223 -> smem
    {
        const float4* src = (const float4*)w_rec;
        float4*       dst = (float4*)w_sm;
#pragma unroll
        for (int i = 0; i < 56; i++) dst[n + (i << 8)] = src[n + (i << 8)];
    }
    // rows 224..255 -> regs, diag masked
    float wreg[32];
#pragma unroll
    for (int j = 0; j < 32; j++) wreg[j] = w_rec[(WROWS + j) * 256 + n];
#pragma unroll
    for (int j = 0; j < 32; j++)
        if (n == WROWS + j) wreg[j] = 0.f;
    w_sm[224 * 256 + n] = 0.f;                    // zero sentinel row
    if (n < 16) cntS[n] = 0;
    __syncthreads();
    if (n < WROWS) w_sm[n * 256 + n] = 0.f;       // diag mask

    float z_self = z0[b * N_ + n];
    float v      = v0[b * N_ + n];
    float a      = a0[b * N_ + n];
    float lsd    = lsd0[b * N_ + n];

    // initial list build (buffer 0)
    unsigned mB = __ballot_sync(0xffffffffu, z_self != 0.f);
    if (w < 7) { if (lane == 0) cntS[w] = __popc(mB); }
    else if (lane == 0) maskH[0] = mB;
    __syncthreads();
    {
        int4 cA = *(const int4*)&cntS[0];
        int4 cB = *(const int4*)&cntS[4];
        if (w < 7) {
            int start = 0;
            if (w > 0) start += cA.x; if (w > 1) start += cA.y;
            if (w > 2) start += cA.z; if (w > 3) start += cA.w;
            if (w > 4) start += cB.x; if (w > 5) start += cB.y;
            if (z_self != 0.f) {
                int r = __popc(mB & ((1u << lane) - 1u));
                flatL[start + r] = n << 10;
            }
        } else {
            int tt = cA.x + cA.y + cA.z + cA.w + cB.x + cB.y + cB.z;
            if (lane < 8 || tt + lane < 32) flatL[tt + lane] = SENT;
            if (lane == 0) totS[0] = tt;
        }
    }

    const float omdv = 1.f - decay_v;
    const float omda = 1.f - decay_a;
    const char*  wpn = (const char*)w_sm + (n << 2);
    const float* xwb = (const float*)g_xw;
    const int    mb0 = b * T_;
    const int    twon = n << 1;

    int m00 = mb0;
    float xw_cur = __ldcs(xwb + (((size_t)(m00 >> 1)) << 9) + twon + (m00 & 1));
    __syncthreads();

#pragma unroll 1
    for (int t = 0; t < T_; t++) {
        const int rb = t & 1, wb = rb ^ 1;

        float xw_next = 0.f;
        if (t + 1 < T_) {
            int mn = mb0 + t + 1;
            xw_next = __ldcs(xwb + (((size_t)(mn >> 1)) << 9) + twon + (mn & 1));
        }

        const int      tot = totS[rb];
        const unsigned mh  = maskH[rb];
        const int*     fl  = flatL + rb * LCAP;

        // Unconditional block read: 8 independent int4 offset broadcasts
        const int4* fc = (const int4*)fl;
        int4 c0 = fc[0], c1 = fc[1], c2 = fc[2], c3 = fc[3];
        int4 c4 = fc[4], c5 = fc[5], c6 = fc[6], c7 = fc[7];

        float av[8];
#pragma unroll
        for (int j = 0; j < 8; j++) av[j] = 0.f;

        // register-held high rows (independent adds, fill load latency)
#pragma unroll
        for (int j = 0; j < 32; j++)
            if (mh & (1u << j)) av[j & 7] += wreg[j];

        // 32 independent weight loads (sentinels add exact 0)
        av[0] += *(const float*)(wpn + c0.x);
        av[1] += *(const float*)(wpn + c0.y);
        av[2] += *(const float*)(wpn + c0.z);
        av[3] += *(const float*)(wpn + c0.w);
        av[4] += *(const float*)(wpn + c1.x);
        av[5] += *(const float*)(wpn + c1.y);
        av[6] += *(const float*)(wpn + c1.z);
        av[7] += *(const float*)(wpn + c1.w);
        av[0] += *(const float*)(wpn + c2.x);
        av[1] += *(const float*)(wpn + c2.y);
        av[2] += *(const float*)(wpn + c2.z);
        av[3] += *(const float*)(wpn + c2.w);
        av[4] += *(const float*)(wpn + c3.x);
        av[5] += *(const float*)(wpn + c3.y);
        av[6] += *(const float*)(wpn + c3.z);
        av[7] += *(const float*)(wpn + c3.w);
        av[0] += *(const float*)(wpn + c4.x);
        av[1] += *(const float*)(wpn + c4.y);
        av[2] += *(const float*)(wpn + c4.z);
        av[3] += *(const float*)(wpn + c4.w);
        av[4] += *(const float*)(wpn + c5.x);
        av[5] += *(const float*)(wpn + c5.y);
        av[6] += *(const float*)(wpn + c5.z);
        av[7] += *(const float*)(wpn + c5.w);
        av[0] += *(const float*)(wpn + c6.x);
        av[1] += *(const float*)(wpn + c6.y);
        av[2] += *(const float*)(wpn + c6.z);
        av[3] += *(const float*)(wpn + c6.w);
        av[4] += *(const float*)(wpn + c7.x);
        av[5] += *(const float*)(wpn + c7.y);
        av[6] += *(const float*)(wpn + c7.z);
        av[7] += *(const float*)(wpn + c7.w);

        // rare tail (tot > 32); sentinel-padded 8 beyond tot
#pragma unroll 1
        for (int j = 32; j < tot; j += 4) {
            int4 o = *(const int4*)(fl + j);
            av[0] += *(const float*)(wpn + o.x);
            av[1] += *(const float*)(wpn + o.y);
            av[2] += *(const float*)(wpn + o.z);
            av[3] += *(const float*)(wpn + o.w);
        }

        const float i_in = __fadd_rn(xw_cur,
            __fadd_rn(__fadd_rn(__fadd_rn(av[0], av[1]), __fadd_rn(av[2], av[3])),
                      __fadd_rn(__fadd_rn(av[4], av[5]), __fadd_rn(av[6], av[7]))));

        // dynamics; spike via compare (thr > 0 always), div off critical path
        float new_a = __fadd_rn(__fmul_rn(decay_a, a), __fmul_rn(omda, z_self));
        float thr   = __fadd_rn(0.03f, __fmul_rn(new_a, 1.8f));
        float new_v = __fadd_rn(
                        __fadd_rn(__fmul_rn(decay_v, v), __fmul_rn(omdv, i_in)),
                        __fmul_rn(-thr, z_self));
        int   spk = (new_v > thr) && (lsd >= 2.f);
        float zf  = spk ? 1.f : 0.f;

        // phase 1: publish counts / high mask (ballot right after spk)
        unsigned m = __ballot_sync(0xffffffffu, spk);
        if (w < 7) { if (lane == 0) cntS[wb * 8 + w] = __popc(m); }
        else if (lane == 0) maskH[wb] = m;

        float new_lsd = __fmul_rn(__fadd_rn(lsd, 1.f), __fadd_rn(1.f, -zf));
        float v_sc    = __fdividef(__fadd_rn(new_v, -thr), thr);
        __syncthreads();

        // outputs [4, T, B, N]
        const size_t ob = ((size_t)t * B_ + b) * N_ + n;
        __stcs(out + ob,            zf);
        __stcs(out + TBN_ + ob,     new_v);
        __stcs(out + 2 * TBN_ + ob, thr);
        __stcs(out + 3 * TBN_ + ob, v_sc);

        // phase 2: prefix + flat write + sentinels
        {
            int4 cA = *(const int4*)&cntS[wb * 8];
            int4 cB = *(const int4*)&cntS[wb * 8 + 4];
            if (w < 7) {
                int start = 0;
                if (w > 0) start += cA.x; if (w > 1) start += cA.y;
                if (w > 2) start += cA.z; if (w > 3) start += cA.w;
                if (w > 4) start += cB.x; if (w > 5) start += cB.y;
                if (spk) {
                    int r = __popc(m & ((1u << lane) - 1u));
                    flatL[wb * LCAP + start + r] = n << 10;
                }
            } else {
                int tt = cA.x + cA.y + cA.z + cA.w + cB.x + cB.y + cB.z;
                if (lane < 8 || tt + lane < 32)
                    flatL[wb * LCAP + tt + lane] = SENT;
                if (lane == 0) totS[wb] = tt;
            }
        }

        z_self = zf; v = new_v; a = new_a; lsd = new_lsd;
        xw_cur = xw_next;
        __syncthreads();
    }
}

// ---------------------------------------------------------------------------
// Launcher (graph-capturable)
// ---------------------------------------------------------------------------
extern "C" void kernel_launch(void* const* d_in, const int* in_sizes, int n_in,
                              void* d_out, int out_size)
{
    const float* x     = (const float*)d_in[0];
    const float* w_in  = (const float*)d_in[1];
    const float* w_rec = (const float*)d_in[2];
    const float* z0    = (const float*)d_in[3];
    const float* v0    = (const float*)d_in[4];
    const float* a0    = (const float*)d_in[5];
    const float* lsd0  = (const float*)d_in[6];
    float* out = (float*)d_out;

    const float decay_v = expf(-1.0f / 20.0f);
    const float decay_a = expf(-1.0f / 20.0f);

    cudaFuncSetAttribute(gemm_xw,
                         cudaFuncAttributeMaxDynamicSharedMemorySize, GEMM_SMEM);
    cudaFuncSetAttribute(lsnn_scan,
                         cudaFuncAttributeMaxDynamicSharedMemorySize, SCAN_SMEM);

    gemm_xw<<<M_ / 128, 256, GEMM_SMEM>>>(x, w_in);
    lsnn_scan<<<B_, 256, SCAN_SMEM>>>(w_rec, z0, v0, a0, lsd0, out,
                                      decay_v, decay_a);
}